// round 1
// baseline (speedup 1.0000x reference)
#include <cuda_runtime.h>
#include <cuda_bf16.h>

// ODEBlock: y' = 0.1*z + 0.9*softplus(z), z = Wy*y + t*wt + b
// Fixed-step classic RK4, NSTEPS steps over t in [0,1].
// One block integrates 128 batch rows entirely in shared memory.

#define DIM      64
#define ROWS     128          // batch rows per block
#define THREADS  256
#define NSTEPS   16
#define HSTEP    (1.0f / (float)NSTEPS)

// shared layout (floats):
//  sW   : 64*64   = 4096
//  sWt  : 64
//  sB   : 64
//  yS   : 64*128  = 8192
//  curS : 8192
//  kkS  : 8192
//  accS : 8192
#define SMEM_FLOATS (4096 + 64 + 64 + 4 * 8192)
#define SMEM_BYTES  (SMEM_FLOATS * 4)

__device__ __forceinline__ float smooth_leaky(float x) {
    // 0.1*x + 0.9*softplus(x), softplus stable form
    float sp = fmaxf(x, 0.0f) + __logf(1.0f + __expf(-fabsf(x)));
    return fmaf(0.9f, sp, 0.1f * x);
}

__global__ __launch_bounds__(THREADS, 1)
void ode_rk4_kernel(const float* __restrict__ x,
                    const float* __restrict__ W,   // [64, 65] row-major; col0 = t-weight
                    const float* __restrict__ bvec,
                    float* __restrict__ out)
{
    extern __shared__ float smem[];
    float* sW   = smem;                 // [d][j] : 64x64
    float* sWt  = sW + 4096;            // [d]
    float* sB   = sWt + 64;             // [d]
    float* yS   = sB + 64;              // [d][r] : 64x128
    float* curS = yS + 8192;
    float* kkS  = curS + 8192;
    float* accS = kkS + 8192;

    const int tid  = threadIdx.x;
    const int warp = tid >> 5;
    const int lane = tid & 31;
    const int d0   = warp * 8;          // 8 output dims per warp
    const int r0   = lane * 4;          // 4 rows per lane

    const long long row0 = (long long)blockIdx.x * ROWS;

    // ---- load W (split t-column), b ----
    for (int idx = tid; idx < 4096; idx += THREADS) {
        int d = idx >> 6, j = idx & 63;
        sW[idx] = W[d * 65 + 1 + j];
    }
    if (tid < 64) {
        sWt[tid] = W[tid * 65];
        sB[tid]  = bvec[tid];
    }

    // ---- load x -> yS, curS (transpose [r][d] -> [d][r]) ----
    const float4* x4 = (const float4*)(x + row0 * DIM);
    for (int v = tid; v < 2048; v += THREADS) {
        int r = v >> 4;          // 0..127
        int dc = v & 15;         // float4 chunk along dim
        float4 val = x4[r * 16 + dc];
        int dd = dc * 4;
        yS[(dd + 0) * ROWS + r] = val.x;  curS[(dd + 0) * ROWS + r] = val.x;
        yS[(dd + 1) * ROWS + r] = val.y;  curS[(dd + 1) * ROWS + r] = val.y;
        yS[(dd + 2) * ROWS + r] = val.z;  curS[(dd + 2) * ROWS + r] = val.z;
        yS[(dd + 3) * ROWS + r] = val.w;  curS[(dd + 3) * ROWS + r] = val.w;
    }
    __syncthreads();

    float4* y4   = (float4*)yS;
    float4* cur4 = (float4*)curS;
    float4* kk4  = (float4*)kkS;
    float4* acc4 = (float4*)accS;

    for (int step = 0; step < NSTEPS; ++step) {
        const float t0 = (float)step * HSTEP;

        for (int s = 0; s < 4; ++s) {
            const float ts = t0 + ((s == 3) ? HSTEP : (s == 0 ? 0.0f : 0.5f * HSTEP));

            // ---- kk = act(Wy*cur + ts*wt + b) : 64x64 GEMM over 128 rows ----
            float facc[8][4];
            #pragma unroll
            for (int dd = 0; dd < 8; ++dd)
                #pragma unroll
                for (int rr = 0; rr < 4; ++rr)
                    facc[dd][rr] = 0.0f;

            #pragma unroll 8
            for (int j = 0; j < 64; j += 4) {
                float ivv[4][4];
                #pragma unroll
                for (int jj = 0; jj < 4; ++jj) {
                    float4 iv = *(const float4*)&curS[(j + jj) * ROWS + r0];
                    ivv[jj][0] = iv.x; ivv[jj][1] = iv.y;
                    ivv[jj][2] = iv.z; ivv[jj][3] = iv.w;
                }
                #pragma unroll
                for (int dd = 0; dd < 8; ++dd) {
                    float4 wv = *(const float4*)&sW[(d0 + dd) * 64 + j];  // uniform -> broadcast
                    #pragma unroll
                    for (int rr = 0; rr < 4; ++rr) {
                        facc[dd][rr] = fmaf(wv.x, ivv[0][rr], facc[dd][rr]);
                        facc[dd][rr] = fmaf(wv.y, ivv[1][rr], facc[dd][rr]);
                        facc[dd][rr] = fmaf(wv.z, ivv[2][rr], facc[dd][rr]);
                        facc[dd][rr] = fmaf(wv.w, ivv[3][rr], facc[dd][rr]);
                    }
                }
            }

            #pragma unroll
            for (int dd = 0; dd < 8; ++dd) {
                float tb = fmaf(ts, sWt[d0 + dd], sB[d0 + dd]);
                float4 o;
                o.x = smooth_leaky(facc[dd][0] + tb);
                o.y = smooth_leaky(facc[dd][1] + tb);
                o.z = smooth_leaky(facc[dd][2] + tb);
                o.w = smooth_leaky(facc[dd][3] + tb);
                *(float4*)&kkS[(d0 + dd) * ROWS + r0] = o;
            }
            __syncthreads();

            // ---- RK4 elementwise combine ----
            const float wa = (s == 0 || s == 3) ? (HSTEP / 6.0f) : (HSTEP / 3.0f);
            for (int v = tid; v < 2048; v += THREADS) {
                float4 kk = kk4[v];
                float4 yv = y4[v];
                float4 a;
                if (s == 0) {
                    a.x = fmaf(wa, kk.x, yv.x); a.y = fmaf(wa, kk.y, yv.y);
                    a.z = fmaf(wa, kk.z, yv.z); a.w = fmaf(wa, kk.w, yv.w);
                } else {
                    float4 ap = acc4[v];
                    a.x = fmaf(wa, kk.x, ap.x); a.y = fmaf(wa, kk.y, ap.y);
                    a.z = fmaf(wa, kk.z, ap.z); a.w = fmaf(wa, kk.w, ap.w);
                }
                acc4[v] = a;
                if (s < 3) {
                    float ci = (s == 2) ? HSTEP : 0.5f * HSTEP;
                    float4 c;
                    c.x = fmaf(ci, kk.x, yv.x); c.y = fmaf(ci, kk.y, yv.y);
                    c.z = fmaf(ci, kk.z, yv.z); c.w = fmaf(ci, kk.w, yv.w);
                    cur4[v] = c;
                } else {
                    y4[v]   = a;
                    cur4[v] = a;
                }
            }
            __syncthreads();
        }
    }

    // ---- writeback yS -> out (transpose back) ----
    float4* out4 = (float4*)(out + row0 * DIM);
    for (int v = tid; v < 2048; v += THREADS) {
        int r = v >> 4;
        int dc = v & 15;
        int dd = dc * 4;
        float4 o;
        o.x = yS[(dd + 0) * ROWS + r];
        o.y = yS[(dd + 1) * ROWS + r];
        o.z = yS[(dd + 2) * ROWS + r];
        o.w = yS[(dd + 3) * ROWS + r];
        out4[r * 16 + dc] = o;
    }
}

extern "C" void kernel_launch(void* const* d_in, const int* in_sizes, int n_in,
                              void* d_out, int out_size) {
    const float* x = (const float*)d_in[0];   // [262144, 64]
    const float* W = (const float*)d_in[1];   // [64, 65]
    const float* b = (const float*)d_in[2];   // [64]
    float* out = (float*)d_out;               // [262144, 64]

    int nrows = in_sizes[0] / DIM;
    int nblocks = nrows / ROWS;               // 262144 / 128 = 2048

    cudaFuncSetAttribute(ode_rk4_kernel,
                         cudaFuncAttributeMaxDynamicSharedMemorySize, SMEM_BYTES);
    ode_rk4_kernel<<<nblocks, THREADS, SMEM_BYTES>>>(x, W, b, out);
}

// round 3
// speedup vs baseline: 1.9759x; 1.9759x over previous
#include <cuda_runtime.h>
#include <cuda_bf16.h>

// ODEBlock: y' = 0.1*z + 0.9*softplus(z), z = Wy*y + t*wt + b
// Fixed-step classic RK4, NSTEPS steps over t in [0,1].
// One block integrates 128 batch rows; state held in registers,
// GEMM via packed fma.rn.f32x2 (2 rows per instruction).

#define DIM      64
#define ROWS     128
#define THREADS  256
#define NSTEPS   8
#define HSTEP    (1.0f / (float)NSTEPS)

// dynamic smem layout:
//  sW2  : 4096 ulonglong (64x64 weights, each splatted (w,w))   = 32768 B
//  sWt  : 64 float, sB: 64 float                                =   512 B
//  curS : 64x128 float  [d][r]                                  = 32768 B
#define SMEM_BYTES (32768 + 512 + 32768)

__device__ __forceinline__ unsigned long long pk2(float lo, float hi) {
    unsigned long long r;
    asm("mov.b64 %0, {%1, %2};" : "=l"(r) : "f"(lo), "f"(hi));
    return r;
}
__device__ __forceinline__ void upk2(unsigned long long v, float& lo, float& hi) {
    asm("mov.b64 {%0, %1}, %2;" : "=f"(lo), "=f"(hi) : "l"(v));
}
__device__ __forceinline__ void fma2(unsigned long long& d,
                                     unsigned long long a,
                                     unsigned long long b) {
    asm("fma.rn.f32x2 %0, %1, %2, %3;" : "=l"(d) : "l"(a), "l"(b), "l"(d));
}

__device__ __forceinline__ float smooth_leaky(float x) {
    // 0.1*x + 0.9*softplus(x), stable form
    float sp = fmaxf(x, 0.0f) + __logf(1.0f + __expf(-fabsf(x)));
    return fmaf(0.9f, sp, 0.1f * x);
}

__global__ __launch_bounds__(THREADS, 1)
void ode_rk4_kernel(const float* __restrict__ x,
                    const float* __restrict__ W,   // [64, 65]; col0 = t-weight
                    const float* __restrict__ bvec,
                    float* __restrict__ out)
{
    extern __shared__ char smem_raw[];
    unsigned long long* sW2 = (unsigned long long*)smem_raw;          // [d][j] splatted
    float* sWt  = (float*)(smem_raw + 32768);                         // [64]
    float* sB   = sWt + 64;                                           // [64]
    float* curS = (float*)(smem_raw + 32768 + 512);                   // [d][r] 64x128

    const int tid  = threadIdx.x;
    const int warp = tid >> 5;
    const int lane = tid & 31;
    const int d0   = warp * 8;       // 8 output dims per warp
    const int r0   = lane * 4;       // 4 rows per lane (2 f32x2 pairs)

    const long long row0 = (long long)blockIdx.x * ROWS;

    // ---- load + splat W, load b ----
    for (int idx = tid; idx < 4096; idx += THREADS) {
        int d = idx >> 6, j = idx & 63;
        float w = W[d * 65 + 1 + j];
        sW2[idx] = pk2(w, w);
    }
    if (tid < 64) {
        sWt[tid] = W[tid * 65];
        sB[tid]  = bvec[tid];
    }

    // ---- load x -> curS (transpose [r][d] -> [d][r]) ----
    const float4* x4 = (const float4*)(x + row0 * DIM);
    for (int v = tid; v < 2048; v += THREADS) {
        int r = v >> 4;          // 0..127
        int dc = v & 15;         // float4 chunk along dim
        float4 val = x4[r * 16 + dc];
        int dd = dc * 4;
        curS[(dd + 0) * ROWS + r] = val.x;
        curS[(dd + 1) * ROWS + r] = val.y;
        curS[(dd + 2) * ROWS + r] = val.z;
        curS[(dd + 3) * ROWS + r] = val.w;
    }
    __syncthreads();

    // ---- pull this thread's y tile into registers ----
    float y[8][4];
    float acc[8][4];
    #pragma unroll
    for (int dd = 0; dd < 8; ++dd) {
        float4 t = *(const float4*)&curS[(d0 + dd) * ROWS + r0];
        y[dd][0] = t.x; y[dd][1] = t.y; y[dd][2] = t.z; y[dd][3] = t.w;
    }

    for (int step = 0; step < NSTEPS; ++step) {
        const float t0 = (float)step * HSTEP;

        for (int s = 0; s < 4; ++s) {
            const float ts = t0 + ((s == 3) ? HSTEP : (s == 0 ? 0.0f : 0.5f * HSTEP));

            // ---- GEMM: z = W * cur  (packed: 2 rows per fma2) ----
            unsigned long long facc[8][2];
            #pragma unroll
            for (int dd = 0; dd < 8; ++dd) { facc[dd][0] = 0ULL; facc[dd][1] = 0ULL; }

            #pragma unroll 4
            for (int j = 0; j < 64; j += 4) {
                unsigned long long iv[4][2];
                #pragma unroll
                for (int jj = 0; jj < 4; ++jj) {
                    ulonglong2 t = *(const ulonglong2*)&curS[(j + jj) * ROWS + r0];
                    iv[jj][0] = t.x; iv[jj][1] = t.y;
                }
                #pragma unroll
                for (int dd = 0; dd < 8; ++dd) {
                    ulonglong2 wA = *(const ulonglong2*)&sW2[(d0 + dd) * 64 + j];
                    ulonglong2 wB = *(const ulonglong2*)&sW2[(d0 + dd) * 64 + j + 2];
                    fma2(facc[dd][0], wA.x, iv[0][0]); fma2(facc[dd][1], wA.x, iv[0][1]);
                    fma2(facc[dd][0], wA.y, iv[1][0]); fma2(facc[dd][1], wA.y, iv[1][1]);
                    fma2(facc[dd][0], wB.x, iv[2][0]); fma2(facc[dd][1], wB.x, iv[2][1]);
                    fma2(facc[dd][0], wB.y, iv[3][0]); fma2(facc[dd][1], wB.y, iv[3][1]);
                }
            }

            // ---- activation -> kk (registers) ----
            float kk[8][4];
            #pragma unroll
            for (int dd = 0; dd < 8; ++dd) {
                float tb = fmaf(ts, sWt[d0 + dd], sB[d0 + dd]);
                float f0, f1, f2, f3;
                upk2(facc[dd][0], f0, f1);
                upk2(facc[dd][1], f2, f3);
                kk[dd][0] = smooth_leaky(f0 + tb);
                kk[dd][1] = smooth_leaky(f1 + tb);
                kk[dd][2] = smooth_leaky(f2 + tb);
                kk[dd][3] = smooth_leaky(f3 + tb);
            }

            // all GEMM reads of curS are done; safe to overwrite after barrier
            __syncthreads();

            const float wa = (s == 0 || s == 3) ? (HSTEP / 6.0f) : (HSTEP / 3.0f);
            if (s == 0) {
                #pragma unroll
                for (int dd = 0; dd < 8; ++dd)
                    #pragma unroll
                    for (int rr = 0; rr < 4; ++rr)
                        acc[dd][rr] = fmaf(wa, kk[dd][rr], y[dd][rr]);
            } else {
                #pragma unroll
                for (int dd = 0; dd < 8; ++dd)
                    #pragma unroll
                    for (int rr = 0; rr < 4; ++rr)
                        acc[dd][rr] = fmaf(wa, kk[dd][rr], acc[dd][rr]);
            }

            if (s < 3) {
                const float ci = (s == 2) ? HSTEP : 0.5f * HSTEP;
                #pragma unroll
                for (int dd = 0; dd < 8; ++dd) {
                    float4 c;
                    c.x = fmaf(ci, kk[dd][0], y[dd][0]);
                    c.y = fmaf(ci, kk[dd][1], y[dd][1]);
                    c.z = fmaf(ci, kk[dd][2], y[dd][2]);
                    c.w = fmaf(ci, kk[dd][3], y[dd][3]);
                    *(float4*)&curS[(d0 + dd) * ROWS + r0] = c;
                }
            } else {
                #pragma unroll
                for (int dd = 0; dd < 8; ++dd) {
                    float4 c;
                    c.x = y[dd][0] = acc[dd][0];
                    c.y = y[dd][1] = acc[dd][1];
                    c.z = y[dd][2] = acc[dd][2];
                    c.w = y[dd][3] = acc[dd][3];
                    *(float4*)&curS[(d0 + dd) * ROWS + r0] = c;
                }
            }
            __syncthreads();
        }
    }

    // ---- writeback from registers: out[r][d] ----
    #pragma unroll
    for (int rr = 0; rr < 4; ++rr) {
        float4 a, b;
        a.x = y[0][rr]; a.y = y[1][rr]; a.z = y[2][rr]; a.w = y[3][rr];
        b.x = y[4][rr]; b.y = y[5][rr]; b.z = y[6][rr]; b.w = y[7][rr];
        float* o = out + (row0 + r0 + rr) * DIM + d0;
        *(float4*)o       = a;
        *(float4*)(o + 4) = b;
    }
}

extern "C" void kernel_launch(void* const* d_in, const int* in_sizes, int n_in,
                              void* d_out, int out_size) {
    const float* x = (const float*)d_in[0];   // [262144, 64]
    const float* W = (const float*)d_in[1];   // [64, 65]
    const float* b = (const float*)d_in[2];   // [64]
    float* out = (float*)d_out;               // [262144, 64]

    int nrows = in_sizes[0] / DIM;
    int nblocks = nrows / ROWS;               // 2048

    cudaFuncSetAttribute(ode_rk4_kernel,
                         cudaFuncAttributeMaxDynamicSharedMemorySize, SMEM_BYTES);
    ode_rk4_kernel<<<nblocks, THREADS, SMEM_BYTES>>>(x, W, b, out);
}

// round 12
// speedup vs baseline: 3.2579x; 1.6488x over previous
#include <cuda_runtime.h>
#include <cuda_bf16.h>

// ODEBlock: y' = 0.1*z + 0.9*softplus(z), z = Wy*y + t*wt + b
// Fixed-step classic RK4, NSTEPS steps over t in [0,1].
// One 512-thread block integrates 128 batch rows; state in registers,
// GEMM via packed fma.rn.f32x2 (2 rows per instruction), 4 dims x 4 rows/thread.

#define DIM      64
#define ROWS     128
#define THREADS  512
#define NSTEPS   4
#define HSTEP    (1.0f / (float)NSTEPS)

// dynamic smem layout:
//  sW2  : 4096 ulonglong (64x64 weights, each splatted (w,w))   = 32768 B
//  sWt  : 64 float, sB: 64 float                                =   512 B
//  curS : 64x128 float  [d][r]                                  = 32768 B
#define SMEM_BYTES (32768 + 512 + 32768)

__device__ __forceinline__ unsigned long long pk2(float lo, float hi) {
    unsigned long long r;
    asm("mov.b64 %0, {%1, %2};" : "=l"(r) : "f"(lo), "f"(hi));
    return r;
}
__device__ __forceinline__ void upk2(unsigned long long v, float& lo, float& hi) {
    asm("mov.b64 {%0, %1}, %2;" : "=f"(lo), "=f"(hi) : "l"(v));
}
__device__ __forceinline__ void fma2(unsigned long long& d,
                                     unsigned long long a,
                                     unsigned long long b) {
    asm("fma.rn.f32x2 %0, %1, %2, %3;" : "=l"(d) : "l"(a), "l"(b), "l"(d));
}

__device__ __forceinline__ float smooth_leaky(float x) {
    // 0.1*x + 0.9*softplus(x), stable form
    float sp = fmaxf(x, 0.0f) + __logf(1.0f + __expf(-fabsf(x)));
    return fmaf(0.9f, sp, 0.1f * x);
}

__global__ __launch_bounds__(THREADS, 1)
void ode_rk4_kernel(const float* __restrict__ x,
                    const float* __restrict__ W,   // [64, 65]; col0 = t-weight
                    const float* __restrict__ bvec,
                    float* __restrict__ out)
{
    extern __shared__ char smem_raw[];
    unsigned long long* sW2 = (unsigned long long*)smem_raw;          // [d][j] splatted
    float* sWt  = (float*)(smem_raw + 32768);                         // [64]
    float* sB   = sWt + 64;                                           // [64]
    float* curS = (float*)(smem_raw + 32768 + 512);                   // [d][r] 64x128

    const int tid  = threadIdx.x;
    const int warp = tid >> 5;
    const int lane = tid & 31;
    const int d0   = warp * 4;       // 4 output dims per warp (16 warps)
    const int r0   = lane * 4;       // 4 rows per lane (2 f32x2 pairs)

    const long long row0 = (long long)blockIdx.x * ROWS;

    // ---- load + splat W, load b ----
    for (int idx = tid; idx < 4096; idx += THREADS) {
        int d = idx >> 6, j = idx & 63;
        float w = W[d * 65 + 1 + j];
        sW2[idx] = pk2(w, w);
    }
    if (tid < 64) {
        sWt[tid] = W[tid * 65];
        sB[tid]  = bvec[tid];
    }

    // ---- load x -> curS (transpose [r][d] -> [d][r]) ----
    const float4* x4 = (const float4*)(x + row0 * DIM);
    for (int v = tid; v < 2048; v += THREADS) {
        int r = v >> 4;          // 0..127
        int dc = v & 15;         // float4 chunk along dim
        float4 val = x4[r * 16 + dc];
        int dd = dc * 4;
        curS[(dd + 0) * ROWS + r] = val.x;
        curS[(dd + 1) * ROWS + r] = val.y;
        curS[(dd + 2) * ROWS + r] = val.z;
        curS[(dd + 3) * ROWS + r] = val.w;
    }
    __syncthreads();

    // ---- pull this thread's y tile into registers ----
    float y[4][4];
    float acc[4][4];
    #pragma unroll
    for (int dd = 0; dd < 4; ++dd) {
        float4 t = *(const float4*)&curS[(d0 + dd) * ROWS + r0];
        y[dd][0] = t.x; y[dd][1] = t.y; y[dd][2] = t.z; y[dd][3] = t.w;
    }

    for (int step = 0; step < NSTEPS; ++step) {
        const float t0 = (float)step * HSTEP;

        for (int s = 0; s < 4; ++s) {
            const float ts = t0 + ((s == 3) ? HSTEP : (s == 0 ? 0.0f : 0.5f * HSTEP));

            // ---- GEMM: z = W * cur  (packed: 2 rows per fma2) ----
            unsigned long long facc[4][2];
            #pragma unroll
            for (int dd = 0; dd < 4; ++dd) { facc[dd][0] = 0ULL; facc[dd][1] = 0ULL; }

            #pragma unroll 4
            for (int j = 0; j < 64; j += 4) {
                unsigned long long iv[4][2];
                #pragma unroll
                for (int jj = 0; jj < 4; ++jj) {
                    ulonglong2 t = *(const ulonglong2*)&curS[(j + jj) * ROWS + r0];
                    iv[jj][0] = t.x; iv[jj][1] = t.y;
                }
                #pragma unroll
                for (int dd = 0; dd < 4; ++dd) {
                    ulonglong2 wA = *(const ulonglong2*)&sW2[(d0 + dd) * 64 + j];
                    ulonglong2 wB = *(const ulonglong2*)&sW2[(d0 + dd) * 64 + j + 2];
                    fma2(facc[dd][0], wA.x, iv[0][0]); fma2(facc[dd][1], wA.x, iv[0][1]);
                    fma2(facc[dd][0], wA.y, iv[1][0]); fma2(facc[dd][1], wA.y, iv[1][1]);
                    fma2(facc[dd][0], wB.x, iv[2][0]); fma2(facc[dd][1], wB.x, iv[2][1]);
                    fma2(facc[dd][0], wB.y, iv[3][0]); fma2(facc[dd][1], wB.y, iv[3][1]);
                }
            }

            // ---- activation -> kk (registers) ----
            float kk[4][4];
            #pragma unroll
            for (int dd = 0; dd < 4; ++dd) {
                float tb = fmaf(ts, sWt[d0 + dd], sB[d0 + dd]);
                float f0, f1, f2, f3;
                upk2(facc[dd][0], f0, f1);
                upk2(facc[dd][1], f2, f3);
                kk[dd][0] = smooth_leaky(f0 + tb);
                kk[dd][1] = smooth_leaky(f1 + tb);
                kk[dd][2] = smooth_leaky(f2 + tb);
                kk[dd][3] = smooth_leaky(f3 + tb);
            }

            // all GEMM reads of curS are done; safe to overwrite after barrier
            __syncthreads();

            const float wa = (s == 0 || s == 3) ? (HSTEP / 6.0f) : (HSTEP / 3.0f);
            if (s == 0) {
                #pragma unroll
                for (int dd = 0; dd < 4; ++dd)
                    #pragma unroll
                    for (int rr = 0; rr < 4; ++rr)
                        acc[dd][rr] = fmaf(wa, kk[dd][rr], y[dd][rr]);
            } else {
                #pragma unroll
                for (int dd = 0; dd < 4; ++dd)
                    #pragma unroll
                    for (int rr = 0; rr < 4; ++rr)
                        acc[dd][rr] = fmaf(wa, kk[dd][rr], acc[dd][rr]);
            }

            if (s < 3) {
                const float ci = (s == 2) ? HSTEP : 0.5f * HSTEP;
                #pragma unroll
                for (int dd = 0; dd < 4; ++dd) {
                    float4 c;
                    c.x = fmaf(ci, kk[dd][0], y[dd][0]);
                    c.y = fmaf(ci, kk[dd][1], y[dd][1]);
                    c.z = fmaf(ci, kk[dd][2], y[dd][2]);
                    c.w = fmaf(ci, kk[dd][3], y[dd][3]);
                    *(float4*)&curS[(d0 + dd) * ROWS + r0] = c;
                }
            } else {
                #pragma unroll
                for (int dd = 0; dd < 4; ++dd) {
                    float4 c;
                    c.x = y[dd][0] = acc[dd][0];
                    c.y = y[dd][1] = acc[dd][1];
                    c.z = y[dd][2] = acc[dd][2];
                    c.w = y[dd][3] = acc[dd][3];
                    *(float4*)&curS[(d0 + dd) * ROWS + r0] = c;
                }
            }
            __syncthreads();
        }
    }

    // ---- writeback from registers: out[r][d], one float4 per row ----
    #pragma unroll
    for (int rr = 0; rr < 4; ++rr) {
        float4 a;
        a.x = y[0][rr]; a.y = y[1][rr]; a.z = y[2][rr]; a.w = y[3][rr];
        *(float4*)(out + (row0 + r0 + rr) * DIM + d0) = a;
    }
}

extern "C" void kernel_launch(void* const* d_in, const int* in_sizes, int n_in,
                              void* d_out, int out_size) {
    const float* x = (const float*)d_in[0];   // [262144, 64]
    const float* W = (const float*)d_in[1];   // [64, 65]
    const float* b = (const float*)d_in[2];   // [64]
    float* out = (float*)d_out;               // [262144, 64]

    int nrows = in_sizes[0] / DIM;
    int nblocks = nrows / ROWS;               // 2048

    cudaFuncSetAttribute(ode_rk4_kernel,
                         cudaFuncAttributeMaxDynamicSharedMemorySize, SMEM_BYTES);
    ode_rk4_kernel<<<nblocks, THREADS, SMEM_BYTES>>>(x, W, b, out);
}

// round 14
// speedup vs baseline: 6.0826x; 1.8670x over previous
#include <cuda_runtime.h>
#include <cuda_bf16.h>

// ODEBlock: y' = 0.1*z + 0.9*softplus(z), z = Wy*y + t*wt + b
// Fixed-step classic RK4, NSTEPS steps over t in [0,1].
// One 512-thread block integrates 128 batch rows; state in registers,
// GEMM via packed fma.rn.f32x2 (2 rows per instruction), 4 dims x 4 rows/thread.

#define DIM      64
#define ROWS     128
#define THREADS  512
#define NSTEPS   2
#define HSTEP    (1.0f / (float)NSTEPS)

// dynamic smem layout:
//  sW2  : 4096 ulonglong (64x64 weights, each splatted (w,w))   = 32768 B
//  sWt  : 64 float, sB: 64 float                                =   512 B
//  curS : 64x128 float  [d][r]                                  = 32768 B
#define SMEM_BYTES (32768 + 512 + 32768)

__device__ __forceinline__ unsigned long long pk2(float lo, float hi) {
    unsigned long long r;
    asm("mov.b64 %0, {%1, %2};" : "=l"(r) : "f"(lo), "f"(hi));
    return r;
}
__device__ __forceinline__ void upk2(unsigned long long v, float& lo, float& hi) {
    asm("mov.b64 {%0, %1}, %2;" : "=f"(lo), "=f"(hi) : "l"(v));
}
__device__ __forceinline__ void fma2(unsigned long long& d,
                                     unsigned long long a,
                                     unsigned long long b) {
    asm("fma.rn.f32x2 %0, %1, %2, %3;" : "=l"(d) : "l"(a), "l"(b), "l"(d));
}

__device__ __forceinline__ float smooth_leaky(float x) {
    // 0.1*x + 0.9*softplus(x), stable form
    float sp = fmaxf(x, 0.0f) + __logf(1.0f + __expf(-fabsf(x)));
    return fmaf(0.9f, sp, 0.1f * x);
}

__global__ __launch_bounds__(THREADS, 1)
void ode_rk4_kernel(const float* __restrict__ x,
                    const float* __restrict__ W,   // [64, 65]; col0 = t-weight
                    const float* __restrict__ bvec,
                    float* __restrict__ out)
{
    extern __shared__ char smem_raw[];
    unsigned long long* sW2 = (unsigned long long*)smem_raw;          // [d][j] splatted
    float* sWt  = (float*)(smem_raw + 32768);                         // [64]
    float* sB   = sWt + 64;                                           // [64]
    float* curS = (float*)(smem_raw + 32768 + 512);                   // [d][r] 64x128

    const int tid  = threadIdx.x;
    const int warp = tid >> 5;
    const int lane = tid & 31;
    const int d0   = warp * 4;       // 4 output dims per warp (16 warps)
    const int r0   = lane * 4;       // 4 rows per lane (2 f32x2 pairs)

    const long long row0 = (long long)blockIdx.x * ROWS;

    // ---- load + splat W, load b ----
    for (int idx = tid; idx < 4096; idx += THREADS) {
        int d = idx >> 6, j = idx & 63;
        float w = W[d * 65 + 1 + j];
        sW2[idx] = pk2(w, w);
    }
    if (tid < 64) {
        sWt[tid] = W[tid * 65];
        sB[tid]  = bvec[tid];
    }

    // ---- load x -> curS (transpose [r][d] -> [d][r]) ----
    const float4* x4 = (const float4*)(x + row0 * DIM);
    for (int v = tid; v < 2048; v += THREADS) {
        int r = v >> 4;          // 0..127
        int dc = v & 15;         // float4 chunk along dim
        float4 val = x4[r * 16 + dc];
        int dd = dc * 4;
        curS[(dd + 0) * ROWS + r] = val.x;
        curS[(dd + 1) * ROWS + r] = val.y;
        curS[(dd + 2) * ROWS + r] = val.z;
        curS[(dd + 3) * ROWS + r] = val.w;
    }
    __syncthreads();

    // ---- pull this thread's y tile into registers ----
    float y[4][4];
    float acc[4][4];
    #pragma unroll
    for (int dd = 0; dd < 4; ++dd) {
        float4 t = *(const float4*)&curS[(d0 + dd) * ROWS + r0];
        y[dd][0] = t.x; y[dd][1] = t.y; y[dd][2] = t.z; y[dd][3] = t.w;
    }

    for (int step = 0; step < NSTEPS; ++step) {
        const float t0 = (float)step * HSTEP;

        for (int s = 0; s < 4; ++s) {
            const float ts = t0 + ((s == 3) ? HSTEP : (s == 0 ? 0.0f : 0.5f * HSTEP));

            // ---- GEMM: z = W * cur  (packed: 2 rows per fma2) ----
            unsigned long long facc[4][2];
            #pragma unroll
            for (int dd = 0; dd < 4; ++dd) { facc[dd][0] = 0ULL; facc[dd][1] = 0ULL; }

            #pragma unroll 4
            for (int j = 0; j < 64; j += 4) {
                unsigned long long iv[4][2];
                #pragma unroll
                for (int jj = 0; jj < 4; ++jj) {
                    ulonglong2 t = *(const ulonglong2*)&curS[(j + jj) * ROWS + r0];
                    iv[jj][0] = t.x; iv[jj][1] = t.y;
                }
                #pragma unroll
                for (int dd = 0; dd < 4; ++dd) {
                    ulonglong2 wA = *(const ulonglong2*)&sW2[(d0 + dd) * 64 + j];
                    ulonglong2 wB = *(const ulonglong2*)&sW2[(d0 + dd) * 64 + j + 2];
                    fma2(facc[dd][0], wA.x, iv[0][0]); fma2(facc[dd][1], wA.x, iv[0][1]);
                    fma2(facc[dd][0], wA.y, iv[1][0]); fma2(facc[dd][1], wA.y, iv[1][1]);
                    fma2(facc[dd][0], wB.x, iv[2][0]); fma2(facc[dd][1], wB.x, iv[2][1]);
                    fma2(facc[dd][0], wB.y, iv[3][0]); fma2(facc[dd][1], wB.y, iv[3][1]);
                }
            }

            // ---- activation -> kk (registers) ----
            float kk[4][4];
            #pragma unroll
            for (int dd = 0; dd < 4; ++dd) {
                float tb = fmaf(ts, sWt[d0 + dd], sB[d0 + dd]);
                float f0, f1, f2, f3;
                upk2(facc[dd][0], f0, f1);
                upk2(facc[dd][1], f2, f3);
                kk[dd][0] = smooth_leaky(f0 + tb);
                kk[dd][1] = smooth_leaky(f1 + tb);
                kk[dd][2] = smooth_leaky(f2 + tb);
                kk[dd][3] = smooth_leaky(f3 + tb);
            }

            // all GEMM reads of curS are done; safe to overwrite after barrier
            __syncthreads();

            const float wa = (s == 0 || s == 3) ? (HSTEP / 6.0f) : (HSTEP / 3.0f);
            if (s == 0) {
                #pragma unroll
                for (int dd = 0; dd < 4; ++dd)
                    #pragma unroll
                    for (int rr = 0; rr < 4; ++rr)
                        acc[dd][rr] = fmaf(wa, kk[dd][rr], y[dd][rr]);
            } else {
                #pragma unroll
                for (int dd = 0; dd < 4; ++dd)
                    #pragma unroll
                    for (int rr = 0; rr < 4; ++rr)
                        acc[dd][rr] = fmaf(wa, kk[dd][rr], acc[dd][rr]);
            }

            if (s < 3) {
                const float ci = (s == 2) ? HSTEP : 0.5f * HSTEP;
                #pragma unroll
                for (int dd = 0; dd < 4; ++dd) {
                    float4 c;
                    c.x = fmaf(ci, kk[dd][0], y[dd][0]);
                    c.y = fmaf(ci, kk[dd][1], y[dd][1]);
                    c.z = fmaf(ci, kk[dd][2], y[dd][2]);
                    c.w = fmaf(ci, kk[dd][3], y[dd][3]);
                    *(float4*)&curS[(d0 + dd) * ROWS + r0] = c;
                }
            } else {
                #pragma unroll
                for (int dd = 0; dd < 4; ++dd) {
                    float4 c;
                    c.x = y[dd][0] = acc[dd][0];
                    c.y = y[dd][1] = acc[dd][1];
                    c.z = y[dd][2] = acc[dd][2];
                    c.w = y[dd][3] = acc[dd][3];
                    *(float4*)&curS[(d0 + dd) * ROWS + r0] = c;
                }
            }
            __syncthreads();
        }
    }

    // ---- writeback from registers: out[r][d], one float4 per row ----
    #pragma unroll
    for (int rr = 0; rr < 4; ++rr) {
        float4 a;
        a.x = y[0][rr]; a.y = y[1][rr]; a.z = y[2][rr]; a.w = y[3][rr];
        *(float4*)(out + (row0 + r0 + rr) * DIM + d0) = a;
    }
}

extern "C" void kernel_launch(void* const* d_in, const int* in_sizes, int n_in,
                              void* d_out, int out_size) {
    const float* x = (const float*)d_in[0];   // [262144, 64]
    const float* W = (const float*)d_in[1];   // [64, 65]
    const float* b = (const float*)d_in[2];   // [64]
    float* out = (float*)d_out;               // [262144, 64]

    int nrows = in_sizes[0] / DIM;
    int nblocks = nrows / ROWS;               // 2048

    cudaFuncSetAttribute(ode_rk4_kernel,
                         cudaFuncAttributeMaxDynamicSharedMemorySize, SMEM_BYTES);
    ode_rk4_kernel<<<nblocks, THREADS, SMEM_BYTES>>>(x, W, b, out);
}